// round 6
// baseline (speedup 1.0000x reference)
#include <cuda_runtime.h>
#include <cuda_bf16.h>
#include <stdint.h>

// Embedding_44994077393181
// out[b,t,:] = W_emb_tok[ argnz(X[b,t,:]) , : ] + X_emb_pos[t,:]
// X: (2,2048,32000) fp32 one-hot; W: (32000,1024) fp32; pos: (2048,1024) fp32
//
// WARP-AUTONOMOUS version: one warp per (b,t) row. Each warp scans its row in
// 1024-float passes (8 independent float4 per lane, MLP=8), detects the hit
// with a single __ballot_sync (zero overshoot, zero barriers, zero smem), and
// performs the fused gather + positional add itself (1024 floats = 8 float4
// per lane). No inter-warp coordination of any kind.

#define VOCAB    32000
#define EMB_DIM  1024
#define CTX      2048
#define NROWS    4096         // BATCH * CTX
#define THREADS  256
#define WPB      8            // warps (rows) per block
#define NQ       8000         // float4 per row (VOCAB/4)
#define NPASS    32           // ceil(8000 / 256)

__global__ __launch_bounds__(THREADS)
void embed_onehot_kernel(const float* __restrict__ X,
                         const float* __restrict__ W,
                         const float* __restrict__ pos,
                         float* __restrict__ out)
{
    const int wid  = threadIdx.x >> 5;
    const int lane = threadIdx.x & 31;
    const int row  = blockIdx.x * WPB + wid;   // 0..4095
    const int t    = row & (CTX - 1);

    const float4* xv = reinterpret_cast<const float4*>(X + (size_t)row * VOCAB);

    int idx = -1;

    #pragma unroll 1
    for (int pass = 0; pass < NPASS; ++pass) {
        const int base = pass * 256;           // float4 offset of this pass

        // 8 independent 16B loads per lane (contiguous 4 KB block per warp).
        float4 v[8];
        #pragma unroll
        for (int j = 0; j < 8; ++j) {
            const int p = base + j * 32 + lane;
            if (p < NQ) {
                v[j] = __ldcs(xv + p);
            } else {
                v[j] = make_float4(0.f, 0.f, 0.f, 0.f);
            }
        }

        int found = -1;
        #pragma unroll
        for (int j = 0; j < 8; ++j) {
            const int i = (base + j * 32 + lane) << 2;
            if (v[j].x != 0.0f) found = i;
            if (v[j].y != 0.0f) found = i + 1;
            if (v[j].z != 0.0f) found = i + 2;
            if (v[j].w != 0.0f) found = i + 3;
        }

        const unsigned m = __ballot_sync(0xffffffffu, found >= 0);
        if (m) {
            const int src = __ffs(m) - 1;      // exactly one lane (one-hot)
            idx = __shfl_sync(0xffffffffu, found, src);
            break;
        }
    }

    // Fused gather + positional add: 1024 floats = 32 lanes * 8 float4.
    const float4* wrow = reinterpret_cast<const float4*>(W   + (size_t)idx * EMB_DIM);
    const float4* prow = reinterpret_cast<const float4*>(pos + (size_t)t   * EMB_DIM);
    float4*       orow = reinterpret_cast<float4*>(out + (size_t)row * EMB_DIM);

    #pragma unroll
    for (int j = 0; j < 8; ++j) {
        const int c = j * 32 + lane;
        const float4 wv = __ldg(wrow + c);
        const float4 pv = __ldg(prow + c);
        float4 o;
        o.x = wv.x + pv.x;
        o.y = wv.y + pv.y;
        o.z = wv.z + pv.z;
        o.w = wv.w + pv.w;
        orow[c] = o;
    }
}

extern "C" void kernel_launch(void* const* d_in, const int* in_sizes, int n_in,
                              void* d_out, int out_size)
{
    const float* X   = (const float*)d_in[0];   // (2,2048,32000)
    const float* W   = (const float*)d_in[1];   // (32000,1024)
    const float* pos = (const float*)d_in[2];   // (2048,1024)
    float* out = (float*)d_out;                 // (2,2048,1024)

    embed_onehot_kernel<<<NROWS / WPB, THREADS>>>(X, W, pos, out);
}

// round 7
// speedup vs baseline: 1.0706x; 1.0706x over previous
#include <cuda_runtime.h>
#include <cuda_bf16.h>
#include <stdint.h>

// Embedding_44994077393181
// out[b,t,:] = W_emb_tok[ argnz(X[b,t,:]) , : ] + X_emb_pos[t,:]
// X: (2,2048,32000) fp32 one-hot; W: (32000,1024) fp32; pos: (2048,1024) fp32
//
// Segment-decomposed scan: work item = (row, segment). 4096 rows x 16 segments
// of 2048 floats = 65536 blocks (128 threads). Each block either skips (global
// per-row flag already set by an earlier segment's finder) or streams its 8 KB
// segment with 4 independent float4 loads/thread -- no internal early exit, no
// mid-scan barriers. blockIdx = s*4096 + r with only ~2368 blocks resident, so
// segment s-1 of a row is guaranteed retired before segment s launches: flags
// are exact (zero overshoot) and active blocks are uniform work (zero decay).
// The finder block sets the flag and does the fused gather + positional add.

#define VOCAB    32000
#define EMB_DIM  1024
#define CTX      2048
#define NROWS    4096         // BATCH * CTX
#define THREADS  128
#define SEGF4    512          // float4 per segment (2048 floats, 8 KB)
#define NSEG     16           // ceil(8000 / 512); last segment is partial (320 f4)
#define NQ       8000         // float4 per row

__device__ int g_flags[NROWS];

__global__ void reset_flags_kernel()
{
    const int i = blockIdx.x * blockDim.x + threadIdx.x;
    if (i < NROWS) g_flags[i] = 0;
}

__global__ __launch_bounds__(THREADS)
void embed_onehot_kernel(const float* __restrict__ X,
                         const float* __restrict__ W,
                         const float* __restrict__ pos,
                         float* __restrict__ out)
{
    const int r   = blockIdx.x & (NROWS - 1);   // row (fast dimension)
    const int s   = blockIdx.x >> 12;           // segment (slow dimension)
    const int tid = threadIdx.x;

    // Skip if an earlier segment of this row already found the one-hot index.
    // Scheduling guarantees (r, s-1) retired before this block launched.
    if (s > 0 && *(volatile const int*)(g_flags + r)) return;

    const float4* xv = reinterpret_cast<const float4*>(X + (size_t)r * VOCAB);
    const int base4  = s * SEGF4;

    // Pure streaming scan of the segment: 4 independent float4 per thread.
    int found = -1;
    #pragma unroll
    for (int j = 0; j < 4; ++j) {
        const int p = base4 + j * THREADS + tid;
        if (p < NQ) {                            // only partial for s == 15
            const float4 v = __ldcs(xv + p);
            const int i = p << 2;
            if (v.x != 0.0f) found = i;
            if (v.y != 0.0f) found = i + 1;
            if (v.z != 0.0f) found = i + 2;
            if (v.w != 0.0f) found = i + 3;
        }
    }

    __shared__ int s_idx;
    if (found >= 0) {
        s_idx = found;                           // exactly one nonzero per row
        *(volatile int*)(g_flags + r) = 1;       // early-out hint for later segments
    }

    // One barrier per block; only the finder block proceeds to the gather.
    if (__syncthreads_or(found >= 0)) {
        const int idx = s_idx;
        const int t   = r & (CTX - 1);

        const float4* wrow = reinterpret_cast<const float4*>(W   + (size_t)idx * EMB_DIM);
        const float4* prow = reinterpret_cast<const float4*>(pos + (size_t)t   * EMB_DIM);
        float4*       orow = reinterpret_cast<float4*>(out + (size_t)r * EMB_DIM);

        #pragma unroll
        for (int j = 0; j < 2; ++j) {
            const int c = j * THREADS + tid;
            const float4 wv = __ldg(wrow + c);
            const float4 pv = __ldg(prow + c);
            float4 o;
            o.x = wv.x + pv.x;
            o.y = wv.y + pv.y;
            o.z = wv.z + pv.z;
            o.w = wv.w + pv.w;
            orow[c] = o;
        }
    }
}

extern "C" void kernel_launch(void* const* d_in, const int* in_sizes, int n_in,
                              void* d_out, int out_size)
{
    const float* X   = (const float*)d_in[0];   // (2,2048,32000)
    const float* W   = (const float*)d_in[1];   // (32000,1024)
    const float* pos = (const float*)d_in[2];   // (2048,1024)
    float* out = (float*)d_out;                 // (2,2048,1024)

    reset_flags_kernel<<<(NROWS + 255) / 256, 256>>>();
    embed_onehot_kernel<<<NROWS * NSEG, THREADS>>>(X, W, pos, out);
}

// round 8
// speedup vs baseline: 1.1584x; 1.0820x over previous
#include <cuda_runtime.h>
#include <cuda_bf16.h>
#include <stdint.h>

// Embedding_44994077393181
// out[b,t,:] = W_emb_tok[ argnz(X[b,t,:]) , : ] + X_emb_pos[t,:]
// X: (2,2048,32000) fp32 one-hot; W: (32000,1024) fp32; pos: (2048,1024) fp32
//
// One 64-thread CTA (2 warps) per (b,t) row. Lock-step early-exit scan in
// 2048-float chunks with 8 independent float4 loads per thread per pass
// (2x the per-warp MLP of the 128-thread version at the same chunk size /
// same expected bytes). Nonzero detection via integer OR-reduce of the raw
// bits (one-hot: 0x0 or 0x3F800000) -- ~70% fewer check ops than FP compares;
// exact index recovered from live registers only on the rare found path.
// Then fused gather + positional add.

#define VOCAB    32000
#define EMB_DIM  1024
#define CTX      2048
#define NROWS    4096         // BATCH * CTX
#define THREADS  64
#define CHUNKF4  512          // float4 per pass = 64 threads * 8  (2048 floats)
#define NPASS    16           // ceil(8000 / 512); last pass partial (320 f4)
#define NQ       8000         // float4 per row

__global__ __launch_bounds__(THREADS)
void embed_onehot_kernel(const float* __restrict__ X,
                         const float* __restrict__ W,
                         const float* __restrict__ pos,
                         float* __restrict__ out)
{
    const int row = blockIdx.x;            // 0..4095  (b = row / CTX, t = row % CTX)
    const int t   = row & (CTX - 1);
    const int tid = threadIdx.x;

    const uint4* xv = reinterpret_cast<const uint4*>(X + (size_t)row * VOCAB);

    __shared__ int s_idx;

    #pragma unroll 1
    for (int pass = 0; pass < NPASS; ++pass) {
        const int base = pass * CHUNKF4;

        // 8 independent 16B loads per thread (8 KB chunk per CTA in flight).
        uint4 v[8];
        #pragma unroll
        for (int j = 0; j < 8; ++j) {
            const int p = base + j * THREADS + tid;
            if (p < NQ) {
                v[j] = __ldcs(xv + p);
            } else {
                v[j] = make_uint4(0u, 0u, 0u, 0u);
            }
        }

        // Cheap detect: integer OR-reduce of raw bits (0x0 vs 0x3F800000).
        uint32_t acc = 0u;
        #pragma unroll
        for (int j = 0; j < 8; ++j)
            acc |= (v[j].x | v[j].y) | (v[j].z | v[j].w);

        // Rare path: pinpoint the element from live registers.
        int found = -1;
        if (acc != 0u) {
            #pragma unroll
            for (int j = 0; j < 8; ++j) {
                const int i = (base + j * THREADS + tid) << 2;
                if (v[j].x) found = i;
                if (v[j].y) found = i + 1;
                if (v[j].z) found = i + 2;
                if (v[j].w) found = i + 3;
            }
            s_idx = found;                 // exactly one nonzero per row
        }

        if (__syncthreads_or(found >= 0)) break;
    }
    __syncthreads();                       // make s_idx visible on the break path

    const int idx = s_idx;

    // Fused gather + positional add: 1024 floats = 64 threads * 4 float4.
    const float4* wrow = reinterpret_cast<const float4*>(W   + (size_t)idx * EMB_DIM);
    const float4* prow = reinterpret_cast<const float4*>(pos + (size_t)t   * EMB_DIM);
    float4*       orow = reinterpret_cast<float4*>(out + (size_t)row * EMB_DIM);

    #pragma unroll
    for (int j = 0; j < 4; ++j) {
        const int c = j * THREADS + tid;
        const float4 wv = __ldg(wrow + c);
        const float4 pv = __ldg(prow + c);
        float4 o;
        o.x = wv.x + pv.x;
        o.y = wv.y + pv.y;
        o.z = wv.z + pv.z;
        o.w = wv.w + pv.w;
        orow[c] = o;
    }
}

extern "C" void kernel_launch(void* const* d_in, const int* in_sizes, int n_in,
                              void* d_out, int out_size)
{
    const float* X   = (const float*)d_in[0];   // (2,2048,32000)
    const float* W   = (const float*)d_in[1];   // (32000,1024)
    const float* pos = (const float*)d_in[2];   // (2048,1024)
    float* out = (float*)d_out;                 // (2,2048,1024)

    embed_onehot_kernel<<<NROWS, THREADS>>>(X, W, pos, out);
}